// round 16
// baseline (speedup 1.0000x reference)
#include <cuda_runtime.h>
#include <cuda_bf16.h>
#include <math.h>
#include <stdint.h>

#define B 32
#define C 512
#define Q 128
#define D 768
#define OD (4*D)
#define NEGBIG (-1e30f)

// ---------------- scratch ----------------
__device__ float g_sim [(size_t)B*C*Q];
__device__ float g_smax[B*C];
__device__ float g_cdash[B*D];
__device__ float g_bq  [B*Q];
__device__ __nv_bfloat16 g_Qh[(size_t)B*Q*D];   // plain ques (for c2q)
__device__ __nv_bfloat16 g_Ql[(size_t)B*Q*D];
__device__ __nv_bfloat16 g_Wh[(size_t)B*Q*D];   // w3*ques (for sim)
__device__ __nv_bfloat16 g_Wl[(size_t)B*Q*D];
__device__ __nv_bfloat16 g_Dh[(size_t)B*C*Q];
__device__ __nv_bfloat16 g_Dl[(size_t)B*C*Q];

// ---------------- helpers ----------------
__device__ __forceinline__ unsigned smem_u32(const void* p) {
    unsigned a;
    asm("{ .reg .u64 tmp; cvta.to.shared.u64 tmp, %1; cvt.u32.u64 %0, tmp; }" : "=r"(a) : "l"(p));
    return a;
}
__device__ __forceinline__ void cp16(void* dst, const void* src) {
    unsigned d = smem_u32(dst);
    asm volatile("cp.async.cg.shared.global [%0], [%1], 16;" :: "r"(d), "l"(src));
}
#define CP_COMMIT() asm volatile("cp.async.commit_group;" ::: "memory")
#define CP_WAIT(n)  asm volatile("cp.async.wait_group %0;" :: "n"(n) : "memory")
__device__ __forceinline__ void ldm_x4(unsigned* r, const void* p) {
    unsigned a = smem_u32(p);
    asm volatile("ldmatrix.sync.aligned.m8n8.x4.shared.b16 {%0,%1,%2,%3}, [%4];"
        : "=r"(r[0]), "=r"(r[1]), "=r"(r[2]), "=r"(r[3]) : "r"(a));
}
__device__ __forceinline__ void ldm_x4t(unsigned* r, const void* p) {
    unsigned a = smem_u32(p);
    asm volatile("ldmatrix.sync.aligned.m8n8.x4.trans.shared.b16 {%0,%1,%2,%3}, [%4];"
        : "=r"(r[0]), "=r"(r[1]), "=r"(r[2]), "=r"(r[3]) : "r"(a));
}
__device__ __forceinline__ void mma_bf16(float* d, const unsigned* a, unsigned b0, unsigned b1) {
    asm volatile("mma.sync.aligned.m16n8k16.row.col.f32.bf16.bf16.f32 "
        "{%0,%1,%2,%3}, {%4,%5,%6,%7}, {%8,%9}, {%0,%1,%2,%3};"
        : "+f"(d[0]), "+f"(d[1]), "+f"(d[2]), "+f"(d[3])
        : "r"(a[0]), "r"(a[1]), "r"(a[2]), "r"(a[3]), "r"(b0), "r"(b1));
}
// truncation split: hi = top-16-bits, lo = RN(bf16) of exact residual
__device__ __forceinline__ void split2(float x0, float x1, unsigned& h, unsigned& l) {
    unsigned u0 = __float_as_uint(x0), u1 = __float_as_uint(x1);
    h = __byte_perm(u0, u1, 0x7632);
    float r0 = x0 - __uint_as_float(u0 & 0xFFFF0000u);
    float r1 = x1 - __uint_as_float(u1 & 0xFFFF0000u);
    asm("cvt.rn.bf16x2.f32 %0, %1, %2;" : "=r"(l) : "f"(r1), "f"(r0));
}

#define SSTRIDE 132

// ================= K0: ques -> plain + w3-scaled bf16 images + q.w2 =================
__global__ __launch_bounds__(256) void k_convQ(const float* __restrict__ ques,
                                               const float* __restrict__ SW) {
    const int b = blockIdx.x;
    const int t = threadIdx.x;
    const int row = t >> 1, half = t & 1;
    const size_t off = ((size_t)(b * Q + row)) * D + half * 384;
    const float* src = ques + off;
    const float* w2 = SW + D + half * 384;
    const float* w3 = SW + 2 * D + half * 384;
    __nv_bfloat16* qh = g_Qh + off;
    __nv_bfloat16* ql = g_Ql + off;
    __nv_bfloat16* wh = g_Wh + off;
    __nv_bfloat16* wl = g_Wl + off;
    float acc = 0.f;
    #pragma unroll 2
    for (int g = 0; g < 48; g++) {
        float4 v0 = *(const float4*)(src + g * 8);
        float4 v1 = *(const float4*)(src + g * 8 + 4);
        float4 w0 = *(const float4*)(w2 + g * 8);
        float4 w1 = *(const float4*)(w2 + g * 8 + 4);
        float4 x0 = *(const float4*)(w3 + g * 8);
        float4 x1 = *(const float4*)(w3 + g * 8 + 4);
        acc += v0.x*w0.x + v0.y*w0.y + v0.z*w0.z + v0.w*w0.w
             + v1.x*w1.x + v1.y*w1.y + v1.z*w1.z + v1.w*w1.w;
        unsigned h0, l0, h1, l1, h2, l2, h3, l3;
        split2(v0.x, v0.y, h0, l0);
        split2(v0.z, v0.w, h1, l1);
        split2(v1.x, v1.y, h2, l2);
        split2(v1.z, v1.w, h3, l3);
        *(uint4*)(qh + g * 8) = make_uint4(h0, h1, h2, h3);
        *(uint4*)(ql + g * 8) = make_uint4(l0, l1, l2, l3);
        split2(v0.x*x0.x, v0.y*x0.y, h0, l0);
        split2(v0.z*x0.z, v0.w*x0.w, h1, l1);
        split2(v1.x*x1.x, v1.y*x1.y, h2, l2);
        split2(v1.z*x1.z, v1.w*x1.w, h3, l3);
        *(uint4*)(wh + g * 8) = make_uint4(h0, h1, h2, h3);
        *(uint4*)(wl + g * 8) = make_uint4(l0, l1, l2, l3);
    }
    acc += __shfl_xor_sync(0xffffffffu, acc, 1);
    if (half == 0) g_bq[b * Q + row] = acc;
}

// ================= K1: sim GEMM (3-stage cp.async; A split w/o w3) =================
#define SIM_STAGE 30720
#define SIM_SMEM (3 * SIM_STAGE)   // 92160
__global__ __launch_bounds__(256, 2) void k_sim_mma(const float* __restrict__ cont,
                                                    const float* __restrict__ SW) {
    extern __shared__ char dbuf[];
    __shared__ float sm_a[64], sm_bq[128];
    float* S = (float*)dbuf;

    const int cb = blockIdx.x, b = blockIdx.y;
    const int t = threadIdx.x, lane = t & 31, wid = t >> 5;
    const int wm = wid & 1, wn = wid >> 1;
    const int arow = t >> 2, acol = (t & 3) * 8;

    if (t < 128) sm_bq[t] = g_bq[b * Q + t];

    const float* Ag = cont + ((size_t)(b * C + cb * 64 + arow)) * D + acol;
    const __nv_bfloat16* Wh = g_Wh + ((size_t)b * Q) * D;
    const __nv_bfloat16* Wl = g_Wl + ((size_t)b * Q) * D;
    const float* w1 = SW;

    float acc[2][4][4];
    #pragma unroll
    for (int i = 0; i < 2; i++)
        #pragma unroll
        for (int j = 0; j < 4; j++)
            #pragma unroll
            for (int k = 0; k < 4; k++) acc[i][j][k] = 0.f;

    float a_part = 0.f;
    float4 ra[2];

    auto AhB = [&](int s) { return (__nv_bfloat16(*)[40])(dbuf + s * SIM_STAGE); };
    auto AlB = [&](int s) { return (__nv_bfloat16(*)[40])(dbuf + s * SIM_STAGE + 5120); };
    auto BhB = [&](int s) { return (__nv_bfloat16(*)[40])(dbuf + s * SIM_STAGE + 10240); };
    auto BlB = [&](int s) { return (__nv_bfloat16(*)[40])(dbuf + s * SIM_STAGE + 20480); };

    auto splitA = [&](int k0, int s) {
        __nv_bfloat16 (*Ah)[40] = AhB(s);
        __nv_bfloat16 (*Al)[40] = AlB(s);
        #pragma unroll
        for (int j = 0; j < 2; j++) {
            int col = acol + j * 4;
            float4 w1v = *(const float4*)(w1 + k0 + col);
            a_part += ra[j].x * w1v.x + ra[j].y * w1v.y + ra[j].z * w1v.z + ra[j].w * w1v.w;
            unsigned h0, l0, h1, l1;
            split2(ra[j].x, ra[j].y, h0, l0);
            split2(ra[j].z, ra[j].w, h1, l1);
            *(unsigned*)&Ah[arow][col]     = h0;  *(unsigned*)&Al[arow][col]     = l0;
            *(unsigned*)&Ah[arow][col + 2] = h1;  *(unsigned*)&Al[arow][col + 2] = l1;
        }
    };
    auto issueB = [&](int k0, int s) {
        __nv_bfloat16 (*Bh)[40] = BhB(s);
        __nv_bfloat16 (*Bl)[40] = BlB(s);
        #pragma unroll
        for (int i = 0; i < 2; i++) {
            int idx = t + i * 256;
            int r = idx >> 2, cl = idx & 3;
            cp16(&Bh[r][cl * 8], Wh + (size_t)r * D + k0 + cl * 8);
            cp16(&Bl[r][cl * 8], Wl + (size_t)r * D + k0 + cl * 8);
        }
    };

    const int NK = D / 32;   // 24
    ra[0] = *(const float4*)(Ag);      ra[1] = *(const float4*)(Ag + 4);
    issueB(0, 0);  CP_COMMIT();
    splitA(0, 0);
    ra[0] = *(const float4*)(Ag + 32); ra[1] = *(const float4*)(Ag + 36);
    issueB(32, 1); CP_COMMIT();
    splitA(32, 1);
    ra[0] = *(const float4*)(Ag + 64); ra[1] = *(const float4*)(Ag + 68);

    for (int k = 0; k < NK; k++) {
        if (k < NK - 1) { CP_WAIT(1); } else { CP_WAIT(0); }
        __syncthreads();
        const int cur = k % 3;
        __nv_bfloat16 (*Ah)[40] = AhB(cur);
        __nv_bfloat16 (*Al)[40] = AlB(cur);
        __nv_bfloat16 (*Bh)[40] = BhB(cur);
        __nv_bfloat16 (*Bl)[40] = BlB(cur);
        #pragma unroll
        for (int kk = 0; kk < 2; kk++) {
            const int kb = kk * 16;
            unsigned afh[2][4], afl[2][4];
            #pragma unroll
            for (int mt = 0; mt < 2; mt++) {
                ldm_x4(afh[mt], &Ah[wm * 32 + mt * 16 + (lane & 15)][kb + (lane >> 4) * 8]);
                ldm_x4(afl[mt], &Al[wm * 32 + mt * 16 + (lane & 15)][kb + (lane >> 4) * 8]);
            }
            #pragma unroll
            for (int ng = 0; ng < 2; ng++) {
                unsigned bfh[4], bfl[4];
                ldm_x4(bfh, &Bh[wn * 32 + ng * 16 + (lane & 15)][kb + (lane >> 4) * 8]);
                ldm_x4(bfl, &Bl[wn * 32 + ng * 16 + (lane & 15)][kb + (lane >> 4) * 8]);
                #pragma unroll
                for (int h = 0; h < 2; h++) {
                    const int nt = ng * 2 + h;
                    #pragma unroll
                    for (int mt = 0; mt < 2; mt++) {
                        mma_bf16(acc[mt][nt], afh[mt], bfh[h], bfh[2 + h]);
                        mma_bf16(acc[mt][nt], afh[mt], bfl[h], bfl[2 + h]);
                        mma_bf16(acc[mt][nt], afl[mt], bfh[h], bfh[2 + h]);
                    }
                }
            }
        }
        if (k + 2 < NK) {
            const int s = (k + 2) % 3;
            issueB((k + 2) * 32, s); CP_COMMIT();
            splitA((k + 2) * 32, s);
            if (k + 3 < NK) {
                ra[0] = *(const float4*)(Ag + (k + 3) * 32);
                ra[1] = *(const float4*)(Ag + (k + 3) * 32 + 4);
            }
        }
    }
    __syncthreads();

    a_part += __shfl_xor_sync(0xffffffffu, a_part, 1);
    a_part += __shfl_xor_sync(0xffffffffu, a_part, 2);
    if ((t & 3) == 0) sm_a[arow] = a_part;

    #pragma unroll
    for (int mt = 0; mt < 2; mt++) {
        const int r0 = wm * 32 + mt * 16 + (lane >> 2);
        #pragma unroll
        for (int nt = 0; nt < 4; nt++) {
            const int q0 = wn * 32 + nt * 8 + (lane & 3) * 2;
            *(float2*)&S[r0 * SSTRIDE + q0]       = make_float2(acc[mt][nt][0], acc[mt][nt][1]);
            *(float2*)&S[(r0 + 8) * SSTRIDE + q0] = make_float2(acc[mt][nt][2], acc[mt][nt][3]);
        }
    }
    __syncthreads();

    float4 bq4 = *(const float4*)&sm_bq[lane * 4];
    #pragma unroll
    for (int r = 0; r < 8; r++) {
        const int row = wid * 8 + r;
        float4 v = *(const float4*)&S[row * SSTRIDE + lane * 4];
        float a = sm_a[row];
        v.x += a + bq4.x; v.y += a + bq4.y; v.z += a + bq4.z; v.w += a + bq4.w;
        float m = fmaxf(fmaxf(v.x, v.y), fmaxf(v.z, v.w));
        #pragma unroll
        for (int o = 16; o; o >>= 1) m = fmaxf(m, __shfl_xor_sync(0xffffffffu, m, o));
        *(float4*)(g_sim + ((size_t)(b * C + cb * 64 + row)) * Q + lane * 4) = v;
        if (lane == 0) g_smax[b * C + cb * 64 + row] = m;
    }
}

// ================= K2: fused middle (online colstats || cweights+cdash) =================
__global__ __launch_bounds__(256) void k_mid(const float* __restrict__ cont,
                                             const int* __restrict__ qmask,
                                             const int* __restrict__ cmask) {
    __shared__ float sh_red[256];
    __shared__ float sh_w[512];
    const int t = threadIdx.x;

    if (blockIdx.x < 128) {
        const int b = blockIdx.x >> 2;
        const int tx = t & 31, ty = t >> 5;
        const int q = (blockIdx.x & 3) * 32 + tx;
        const int qm = qmask[b * Q + q];
        float (*redm)[32] = (float (*)[32])sh_red;
        float (*reds)[32] = (float (*)[32])sh_w;   // reuse sh_w for sums
        // online max+sum in ONE pass
        float m = -3.4e38f, s = 0.f;
        for (int c = ty; c < C; c += 8) {
            float v = g_sim[((size_t)(b * C + c)) * Q + q];
            float ms = qm ? v : NEGBIG;
            float mn = fmaxf(m, ms);
            s = s * expf(m - mn) + expf(ms - mn);
            m = mn;
        }
        redm[ty][tx] = m;
        reds[ty][tx] = s;
        __syncthreads();
        if (ty == 0) {
            float M = m;
            #pragma unroll
            for (int k = 1; k < 8; k++) M = fmaxf(M, redm[k][tx]);
            float S = 0.f;
            #pragma unroll
            for (int k = 0; k < 8; k++) S += reds[k][tx] * expf(redm[k][tx] - M);
            redm[0][tx] = M;
            reds[0][tx] = 1.f / S;
        }
        __syncthreads();
        const float M  = redm[0][tx];
        const float rs = reds[0][tx];
        for (int c = ty; c < C; c += 8) {
            size_t idx = ((size_t)(b * C + c)) * Q + q;
            float v = g_sim[idx];
            float x = expf((qm ? v : NEGBIG) - M) * rs;
            unsigned u = __float_as_uint(x);
            unsigned hb = u & 0xFFFF0000u;
            float r2 = x - __uint_as_float(hb);
            __nv_bfloat16 l = __float2bfloat16(r2);
            unsigned short hs = (unsigned short)(u >> 16);
            g_Dh[idx] = *(__nv_bfloat16*)&hs;
            g_Dl[idx] = l;
        }
    } else {
        const int id = blockIdx.x - 128;
        const int b = id / 12, dchunk = id % 12;
        float s0 = g_smax[b * C + t], s1 = g_smax[b * C + 256 + t];
        float ms0 = cmask[b * C + t] ? s0 : NEGBIG;
        float ms1 = cmask[b * C + 256 + t] ? s1 : NEGBIG;
        sh_red[t] = fmaxf(ms0, ms1);
        __syncthreads();
        for (int o = 128; o; o >>= 1) {
            if (t < o) sh_red[t] = fmaxf(sh_red[t], sh_red[t + o]);
            __syncthreads();
        }
        float M = sh_red[0];
        __syncthreads();
        float e0 = expf(ms0 - M), e1 = expf(ms1 - M);
        sh_red[t] = e0 + e1;
        __syncthreads();
        for (int o = 128; o; o >>= 1) {
            if (t < o) sh_red[t] += sh_red[t + o];
            __syncthreads();
        }
        float rS = 1.f / sh_red[0];
        sh_w[t] = e0 * rS;
        sh_w[256 + t] = e1 * rS;
        __syncthreads();
        const int d0 = dchunk * 64;
        const int dl = t & 63, cs = t >> 6;
        float acc = 0.f;
        const float* base = cont + ((size_t)(b * C + cs * 128)) * D + d0 + dl;
        const float* wp = &sh_w[cs * 128];
        #pragma unroll 4
        for (int c = 0; c < 128; c++) acc += wp[c] * base[(size_t)c * D];
        float (*red2)[64] = (float (*)[64])sh_red;
        red2[cs][dl] = acc;
        __syncthreads();
        if (t < 64)
            g_cdash[b * D + d0 + t] = (red2[0][t] + red2[1][t]) + (red2[2][t] + red2[3][t]);
    }
}

// ================= K3: c2q GEMM (3-stage cp.async) + epilogue =================
#define C2Q_STAGE 27648
#define C2Q_SMEM (3 * C2Q_STAGE)   // 82944
__global__ __launch_bounds__(256, 2) void k_c2q_mma(const float* __restrict__ cont,
                                                    float* __restrict__ out) {
    extern __shared__ char dbuf[];
    __shared__ float sm_cd[128];
    float* S = (float*)dbuf;

    const int cb = blockIdx.x, dt = blockIdx.y, b = blockIdx.z;
    const int t = threadIdx.x, lane = t & 31, wid = t >> 5;
    const int wm = wid & 1, wn = wid >> 1;

    if (t < 128) sm_cd[t] = g_cdash[b * D + dt * 128 + t];

    const __nv_bfloat16* Dh = g_Dh + ((size_t)(b * C + cb * 64)) * Q;
    const __nv_bfloat16* Dl = g_Dl + ((size_t)(b * C + cb * 64)) * Q;
    const __nv_bfloat16* Qh = g_Qh + ((size_t)b * Q) * D + dt * 128;
    const __nv_bfloat16* Ql = g_Ql + ((size_t)b * Q) * D + dt * 128;

    auto AhB = [&](int s) { return (__nv_bfloat16(*)[40])(dbuf + s * C2Q_STAGE); };
    auto AlB = [&](int s) { return (__nv_bfloat16(*)[40])(dbuf + s * C2Q_STAGE + 5120); };
    auto BhB = [&](int s) { return (__nv_bfloat16(*)[136])(dbuf + s * C2Q_STAGE + 10240); };
    auto BlB = [&](int s) { return (__nv_bfloat16(*)[136])(dbuf + s * C2Q_STAGE + 18944); };

    const int ar = t >> 2, acl = t & 3;
    auto issueChunk = [&](int k0, int s) {
        cp16(&AhB(s)[ar][acl * 8], Dh + (size_t)ar * Q + k0 + acl * 8);
        cp16(&AlB(s)[ar][acl * 8], Dl + (size_t)ar * Q + k0 + acl * 8);
        __nv_bfloat16 (*Bh)[136] = BhB(s);
        __nv_bfloat16 (*Bl)[136] = BlB(s);
        #pragma unroll
        for (int i = 0; i < 2; i++) {
            int idx = t + i * 256;
            int r = idx >> 4, cl = idx & 15;
            cp16(&Bh[r][cl * 8], Qh + (size_t)(k0 + r) * D + cl * 8);
            cp16(&Bl[r][cl * 8], Ql + (size_t)(k0 + r) * D + cl * 8);
        }
    };

    float acc[2][4][4];
    #pragma unroll
    for (int i = 0; i < 2; i++)
        #pragma unroll
        for (int j = 0; j < 4; j++)
            #pragma unroll
            for (int k = 0; k < 4; k++) acc[i][j][k] = 0.f;

    issueChunk(0, 0);  CP_COMMIT();
    issueChunk(32, 1); CP_COMMIT();

    #pragma unroll
    for (int k = 0; k < 4; k++) {
        if (k < 3) { CP_WAIT(1); } else { CP_WAIT(0); }
        __syncthreads();
        const int cur = k % 3;
        __nv_bfloat16 (*Ah)[40]  = AhB(cur);
        __nv_bfloat16 (*Al)[40]  = AlB(cur);
        __nv_bfloat16 (*Bh)[136] = BhB(cur);
        __nv_bfloat16 (*Bl)[136] = BlB(cur);
        #pragma unroll
        for (int kk = 0; kk < 2; kk++) {
            const int kb = kk * 16;
            unsigned afh[2][4], afl[2][4];
            #pragma unroll
            for (int mt = 0; mt < 2; mt++) {
                ldm_x4(afh[mt], &Ah[wm * 32 + mt * 16 + (lane & 15)][kb + (lane >> 4) * 8]);
                ldm_x4(afl[mt], &Al[wm * 32 + mt * 16 + (lane & 15)][kb + (lane >> 4) * 8]);
            }
            #pragma unroll
            for (int ng = 0; ng < 2; ng++) {
                unsigned bfh[4], bfl[4];
                ldm_x4t(bfh, &Bh[kb + (lane & 15)][wn * 32 + ng * 16 + (lane >> 4) * 8]);
                ldm_x4t(bfl, &Bl[kb + (lane & 15)][wn * 32 + ng * 16 + (lane >> 4) * 8]);
                #pragma unroll
                for (int h = 0; h < 2; h++) {
                    const int nt = ng * 2 + h;
                    #pragma unroll
                    for (int mt = 0; mt < 2; mt++) {
                        mma_bf16(acc[mt][nt], afh[mt], bfh[2 * h], bfh[2 * h + 1]);
                        mma_bf16(acc[mt][nt], afh[mt], bfl[2 * h], bfl[2 * h + 1]);
                        mma_bf16(acc[mt][nt], afl[mt], bfh[2 * h], bfh[2 * h + 1]);
                    }
                }
            }
        }
        if (k + 2 < 4) { issueChunk((k + 2) * 32, (k + 2) % 3); CP_COMMIT(); }
    }
    __syncthreads();

    #pragma unroll
    for (int mt = 0; mt < 2; mt++) {
        const int r0 = wm * 32 + mt * 16 + (lane >> 2);
        #pragma unroll
        for (int nt = 0; nt < 4; nt++) {
            const int d0 = wn * 32 + nt * 8 + (lane & 3) * 2;
            *(float2*)&S[r0 * SSTRIDE + d0]       = make_float2(acc[mt][nt][0], acc[mt][nt][1]);
            *(float2*)&S[(r0 + 8) * SSTRIDE + d0] = make_float2(acc[mt][nt][2], acc[mt][nt][3]);
        }
    }
    __syncthreads();

    float4 cd = *(const float4*)&sm_cd[lane * 4];
    const float* cbase = cont + ((size_t)(b * C + cb * 64 + wid * 8)) * D + dt * 128 + lane * 4;
    float4 ct_next = *(const float4*)(cbase);
    #pragma unroll
    for (int r = 0; r < 8; r++) {
        float4 ct = ct_next;
        if (r + 1 < 8) ct_next = *(const float4*)(cbase + (size_t)(r + 1) * D);
        const int row = wid * 8 + r;
        const int c = cb * 64 + row;
        float4 cq = *(const float4*)&S[row * SSTRIDE + lane * 4];
        float4 m1 = make_float4(ct.x * cq.x, ct.y * cq.y, ct.z * cq.z, ct.w * cq.w);
        float4 m2 = make_float4(ct.x * cd.x, ct.y * cd.y, ct.z * cd.z, ct.w * cd.w);
        float* ob = out + ((size_t)(b * C + c)) * OD + dt * 128 + lane * 4;
        *(float4*)(ob)         = ct;
        *(float4*)(ob + D)     = cq;
        *(float4*)(ob + 2 * D) = m1;
        *(float4*)(ob + 3 * D) = m2;
    }
}

// ---------------- launch ----------------
extern "C" void kernel_launch(void* const* d_in, const int* in_sizes, int n_in,
                              void* d_out, int out_size) {
    const float* cont  = (const float*)d_in[0];
    const int*   cmask = (const int*)d_in[1];
    const float* ques  = (const float*)d_in[2];
    const int*   qmask = (const int*)d_in[3];
    const float* SW    = (const float*)d_in[4];
    float* out = (float*)d_out;
    (void)in_sizes; (void)n_in; (void)out_size;

    cudaFuncSetAttribute(k_sim_mma, cudaFuncAttributeMaxDynamicSharedMemorySize, SIM_SMEM);
    cudaFuncSetAttribute(k_c2q_mma, cudaFuncAttributeMaxDynamicSharedMemorySize, C2Q_SMEM);

    {                           k_convQ<<<B, 256>>>(ques, SW); }
    {   dim3 g(C / 64, B);      k_sim_mma<<<g, 256, SIM_SMEM>>>(cont, SW); }
    {                           k_mid<<<512, 256>>>(cont, qmask, cmask); }
    {   dim3 g(C / 64, 6, B);   k_c2q_mma<<<g, 256, C2Q_SMEM>>>(cont, out); }
}

// round 17
// speedup vs baseline: 1.3869x; 1.3869x over previous
#include <cuda_runtime.h>
#include <cuda_bf16.h>
#include <math.h>
#include <stdint.h>

#define B 32
#define C 512
#define Q 128
#define D 768
#define OD (4*D)
#define NEGBIG (-1e30f)

// ---------------- scratch ----------------
__device__ float g_sim [(size_t)B*C*Q];
__device__ float g_smax[B*C];
__device__ float g_cdash[B*D];
__device__ float g_bq  [B*Q];
__device__ __nv_bfloat16 g_Qh[(size_t)B*Q*D];
__device__ __nv_bfloat16 g_Ql[(size_t)B*Q*D];
__device__ __nv_bfloat16 g_Dh[(size_t)B*C*Q];
__device__ __nv_bfloat16 g_Dl[(size_t)B*C*Q];

// ---------------- helpers ----------------
__device__ __forceinline__ unsigned smem_u32(const void* p) {
    unsigned a;
    asm("{ .reg .u64 tmp; cvta.to.shared.u64 tmp, %1; cvt.u32.u64 %0, tmp; }" : "=r"(a) : "l"(p));
    return a;
}
__device__ __forceinline__ void cp16(void* dst, const void* src) {
    unsigned d = smem_u32(dst);
    asm volatile("cp.async.cg.shared.global [%0], [%1], 16;" :: "r"(d), "l"(src));
}
#define CP_COMMIT() asm volatile("cp.async.commit_group;" ::: "memory")
#define CP_WAIT(n)  asm volatile("cp.async.wait_group %0;" :: "n"(n) : "memory")
__device__ __forceinline__ void ldm_x4(unsigned* r, const void* p) {
    unsigned a = smem_u32(p);
    asm volatile("ldmatrix.sync.aligned.m8n8.x4.shared.b16 {%0,%1,%2,%3}, [%4];"
        : "=r"(r[0]), "=r"(r[1]), "=r"(r[2]), "=r"(r[3]) : "r"(a));
}
__device__ __forceinline__ void ldm_x4t(unsigned* r, const void* p) {
    unsigned a = smem_u32(p);
    asm volatile("ldmatrix.sync.aligned.m8n8.x4.trans.shared.b16 {%0,%1,%2,%3}, [%4];"
        : "=r"(r[0]), "=r"(r[1]), "=r"(r[2]), "=r"(r[3]) : "r"(a));
}
__device__ __forceinline__ void mma_bf16(float* d, const unsigned* a, unsigned b0, unsigned b1) {
    asm volatile("mma.sync.aligned.m16n8k16.row.col.f32.bf16.bf16.f32 "
        "{%0,%1,%2,%3}, {%4,%5,%6,%7}, {%8,%9}, {%0,%1,%2,%3};"
        : "+f"(d[0]), "+f"(d[1]), "+f"(d[2]), "+f"(d[3])
        : "r"(a[0]), "r"(a[1]), "r"(a[2]), "r"(a[3]), "r"(b0), "r"(b1));
}
// truncation split: hi = top-16-bits, lo = RN(bf16) of exact residual
__device__ __forceinline__ void split2(float x0, float x1, unsigned& h, unsigned& l) {
    unsigned u0 = __float_as_uint(x0), u1 = __float_as_uint(x1);
    h = __byte_perm(u0, u1, 0x7632);
    float r0 = x0 - __uint_as_float(u0 & 0xFFFF0000u);
    float r1 = x1 - __uint_as_float(u1 & 0xFFFF0000u);
    asm("cvt.rn.bf16x2.f32 %0, %1, %2;" : "=r"(l) : "f"(r1), "f"(r0));
}

#define SSTRIDE 132

// ================= K0: ques -> bf16 hi/lo images + q.w2 (128 blocks) =================
__global__ __launch_bounds__(256) void k_convQ(const float* __restrict__ ques,
                                               const float* __restrict__ SW) {
    const int b = blockIdx.x >> 2, qg = blockIdx.x & 3;
    const int t = threadIdx.x;
    const int row = qg * 32 + (t >> 3);      // 32 rows per block
    const int seg = t & 7;                   // 8 threads per row, 96 cols each
    const size_t off = ((size_t)(b * Q + row)) * D + seg * 96;
    const float* src = ques + off;
    const float* w2 = SW + D + seg * 96;
    __nv_bfloat16* dh = g_Qh + off;
    __nv_bfloat16* dl = g_Ql + off;
    float acc = 0.f;
    #pragma unroll 4
    for (int g = 0; g < 12; g++) {
        float4 v0 = *(const float4*)(src + g * 8);
        float4 v1 = *(const float4*)(src + g * 8 + 4);
        float4 w0 = *(const float4*)(w2 + g * 8);
        float4 w1 = *(const float4*)(w2 + g * 8 + 4);
        acc += v0.x*w0.x + v0.y*w0.y + v0.z*w0.z + v0.w*w0.w
             + v1.x*w1.x + v1.y*w1.y + v1.z*w1.z + v1.w*w1.w;
        unsigned h0, l0, h1, l1, h2, l2, h3, l3;
        split2(v0.x, v0.y, h0, l0);
        split2(v0.z, v0.w, h1, l1);
        split2(v1.x, v1.y, h2, l2);
        split2(v1.z, v1.w, h3, l3);
        *(uint4*)(dh + g * 8) = make_uint4(h0, h1, h2, h3);
        *(uint4*)(dl + g * 8) = make_uint4(l0, l1, l2, l3);
    }
    acc += __shfl_xor_sync(0xffffffffu, acc, 1);
    acc += __shfl_xor_sync(0xffffffffu, acc, 2);
    acc += __shfl_xor_sync(0xffffffffu, acc, 4);
    if (seg == 0) g_bq[b * Q + row] = acc;
}

// ================= K1: sim GEMM (3-stage cp.async, 1 sync/chunk) =================
#define SIM_STAGE 30720
#define SIM_SMEM (3 * SIM_STAGE)   // 92160
__global__ __launch_bounds__(256, 2) void k_sim_mma(const float* __restrict__ cont,
                                                    const float* __restrict__ SW) {
    extern __shared__ char dbuf[];
    __shared__ float sm_a[64], sm_bq[128];
    float* S = (float*)dbuf;

    const int cb = blockIdx.x, b = blockIdx.y;
    const int t = threadIdx.x, lane = t & 31, wid = t >> 5;
    const int wm = wid & 1, wn = wid >> 1;
    const int arow = t >> 2, acol = (t & 3) * 8;

    if (t < 128) sm_bq[t] = g_bq[b * Q + t];

    const float* Ag = cont + ((size_t)(b * C + cb * 64 + arow)) * D + acol;
    const __nv_bfloat16* Qh = g_Qh + ((size_t)b * Q) * D;
    const __nv_bfloat16* Ql = g_Ql + ((size_t)b * Q) * D;
    const float* w1 = SW;
    const float* w3 = SW + 2 * D;

    float acc[2][4][4];
    #pragma unroll
    for (int i = 0; i < 2; i++)
        #pragma unroll
        for (int j = 0; j < 4; j++)
            #pragma unroll
            for (int k = 0; k < 4; k++) acc[i][j][k] = 0.f;

    float a_part = 0.f;
    float4 ra[2];

    auto AhB = [&](int s) { return (__nv_bfloat16(*)[40])(dbuf + s * SIM_STAGE); };
    auto AlB = [&](int s) { return (__nv_bfloat16(*)[40])(dbuf + s * SIM_STAGE + 5120); };
    auto BhB = [&](int s) { return (__nv_bfloat16(*)[40])(dbuf + s * SIM_STAGE + 10240); };
    auto BlB = [&](int s) { return (__nv_bfloat16(*)[40])(dbuf + s * SIM_STAGE + 20480); };

    auto splitA = [&](int k0, int s) {
        __nv_bfloat16 (*Ah)[40] = AhB(s);
        __nv_bfloat16 (*Al)[40] = AlB(s);
        #pragma unroll
        for (int j = 0; j < 2; j++) {
            int col = acol + j * 4;
            float4 w3v = *(const float4*)(w3 + k0 + col);
            float4 w1v = *(const float4*)(w1 + k0 + col);
            a_part += ra[j].x * w1v.x + ra[j].y * w1v.y + ra[j].z * w1v.z + ra[j].w * w1v.w;
            unsigned h0, l0, h1, l1;
            split2(ra[j].x * w3v.x, ra[j].y * w3v.y, h0, l0);
            split2(ra[j].z * w3v.z, ra[j].w * w3v.w, h1, l1);
            *(unsigned*)&Ah[arow][col]     = h0;  *(unsigned*)&Al[arow][col]     = l0;
            *(unsigned*)&Ah[arow][col + 2] = h1;  *(unsigned*)&Al[arow][col + 2] = l1;
        }
    };
    auto issueB = [&](int k0, int s) {
        __nv_bfloat16 (*Bh)[40] = BhB(s);
        __nv_bfloat16 (*Bl)[40] = BlB(s);
        #pragma unroll
        for (int i = 0; i < 2; i++) {
            int idx = t + i * 256;
            int r = idx >> 2, cl = idx & 3;
            cp16(&Bh[r][cl * 8], Qh + (size_t)r * D + k0 + cl * 8);
            cp16(&Bl[r][cl * 8], Ql + (size_t)r * D + k0 + cl * 8);
        }
    };

    const int NK = D / 32;   // 24
    ra[0] = *(const float4*)(Ag);      ra[1] = *(const float4*)(Ag + 4);
    issueB(0, 0);  CP_COMMIT();
    splitA(0, 0);
    ra[0] = *(const float4*)(Ag + 32); ra[1] = *(const float4*)(Ag + 36);
    issueB(32, 1); CP_COMMIT();
    splitA(32, 1);
    ra[0] = *(const float4*)(Ag + 64); ra[1] = *(const float4*)(Ag + 68);

    for (int k = 0; k < NK; k++) {
        if (k < NK - 1) { CP_WAIT(1); } else { CP_WAIT(0); }
        __syncthreads();
        const int cur = k % 3;
        __nv_bfloat16 (*Ah)[40] = AhB(cur);
        __nv_bfloat16 (*Al)[40] = AlB(cur);
        __nv_bfloat16 (*Bh)[40] = BhB(cur);
        __nv_bfloat16 (*Bl)[40] = BlB(cur);
        #pragma unroll
        for (int kk = 0; kk < 2; kk++) {
            const int kb = kk * 16;
            unsigned afh[2][4], afl[2][4];
            #pragma unroll
            for (int mt = 0; mt < 2; mt++) {
                ldm_x4(afh[mt], &Ah[wm * 32 + mt * 16 + (lane & 15)][kb + (lane >> 4) * 8]);
                ldm_x4(afl[mt], &Al[wm * 32 + mt * 16 + (lane & 15)][kb + (lane >> 4) * 8]);
            }
            #pragma unroll
            for (int ng = 0; ng < 2; ng++) {
                unsigned bfh[4], bfl[4];
                ldm_x4(bfh, &Bh[wn * 32 + ng * 16 + (lane & 15)][kb + (lane >> 4) * 8]);
                ldm_x4(bfl, &Bl[wn * 32 + ng * 16 + (lane & 15)][kb + (lane >> 4) * 8]);
                #pragma unroll
                for (int h = 0; h < 2; h++) {
                    const int nt = ng * 2 + h;
                    #pragma unroll
                    for (int mt = 0; mt < 2; mt++) {
                        mma_bf16(acc[mt][nt], afh[mt], bfh[h], bfh[2 + h]);
                        mma_bf16(acc[mt][nt], afh[mt], bfl[h], bfl[2 + h]);
                        mma_bf16(acc[mt][nt], afl[mt], bfh[h], bfh[2 + h]);
                    }
                }
            }
        }
        if (k + 2 < NK) {
            const int s = (k + 2) % 3;
            issueB((k + 2) * 32, s); CP_COMMIT();
            splitA((k + 2) * 32, s);
            if (k + 3 < NK) {
                ra[0] = *(const float4*)(Ag + (k + 3) * 32);
                ra[1] = *(const float4*)(Ag + (k + 3) * 32 + 4);
            }
        }
    }
    __syncthreads();

    a_part += __shfl_xor_sync(0xffffffffu, a_part, 1);
    a_part += __shfl_xor_sync(0xffffffffu, a_part, 2);
    if ((t & 3) == 0) sm_a[arow] = a_part;

    #pragma unroll
    for (int mt = 0; mt < 2; mt++) {
        const int r0 = wm * 32 + mt * 16 + (lane >> 2);
        #pragma unroll
        for (int nt = 0; nt < 4; nt++) {
            const int q0 = wn * 32 + nt * 8 + (lane & 3) * 2;
            *(float2*)&S[r0 * SSTRIDE + q0]       = make_float2(acc[mt][nt][0], acc[mt][nt][1]);
            *(float2*)&S[(r0 + 8) * SSTRIDE + q0] = make_float2(acc[mt][nt][2], acc[mt][nt][3]);
        }
    }
    __syncthreads();

    float4 bq4 = *(const float4*)&sm_bq[lane * 4];
    #pragma unroll
    for (int r = 0; r < 8; r++) {
        const int row = wid * 8 + r;
        float4 v = *(const float4*)&S[row * SSTRIDE + lane * 4];
        float a = sm_a[row];
        v.x += a + bq4.x; v.y += a + bq4.y; v.z += a + bq4.z; v.w += a + bq4.w;
        float m = fmaxf(fmaxf(v.x, v.y), fmaxf(v.z, v.w));
        #pragma unroll
        for (int o = 16; o; o >>= 1) m = fmaxf(m, __shfl_xor_sync(0xffffffffu, m, o));
        *(float4*)(g_sim + ((size_t)(b * C + cb * 64 + row)) * Q + lane * 4) = v;
        if (lane == 0) g_smax[b * C + cb * 64 + row] = m;
    }
}

// ================= K2: fused middle (colstats || cweights+cdash) =================
__global__ __launch_bounds__(256) void k_mid(const float* __restrict__ cont,
                                             const int* __restrict__ qmask,
                                             const int* __restrict__ cmask) {
    __shared__ float sh_red[256];
    __shared__ float sh_w[512];
    const int t = threadIdx.x;

    if (blockIdx.x < 128) {
        const int b = blockIdx.x >> 2;
        const int tx = t & 31, ty = t >> 5;
        const int q = (blockIdx.x & 3) * 32 + tx;
        const int qm = qmask[b * Q + q];
        float (*red)[32] = (float (*)[32])sh_red;
        float m = -3.4e38f;
        for (int c = ty; c < C; c += 8) {
            float v = g_sim[((size_t)(b * C + c)) * Q + q];
            m = fmaxf(m, qm ? v : NEGBIG);
        }
        red[ty][tx] = m;
        __syncthreads();
        if (ty == 0) {
            #pragma unroll
            for (int k = 1; k < 8; k++) m = fmaxf(m, red[k][tx]);
            red[0][tx] = m;
        }
        __syncthreads();
        m = red[0][tx];
        __syncthreads();
        float s = 0.f;
        for (int c = ty; c < C; c += 8) {
            float v = g_sim[((size_t)(b * C + c)) * Q + q];
            s += expf((qm ? v : NEGBIG) - m);
        }
        red[ty][tx] = s;
        __syncthreads();
        if (ty == 0) {
            #pragma unroll
            for (int k = 1; k < 8; k++) s += red[k][tx];
            red[0][tx] = 1.f / s;
        }
        __syncthreads();
        const float rs = red[0][tx];
        for (int c = ty; c < C; c += 8) {
            size_t idx = ((size_t)(b * C + c)) * Q + q;
            float v = g_sim[idx];
            float x = expf((qm ? v : NEGBIG) - m) * rs;
            unsigned u = __float_as_uint(x);
            unsigned hb = u & 0xFFFF0000u;
            float r2 = x - __uint_as_float(hb);
            __nv_bfloat16 l = __float2bfloat16(r2);
            unsigned short hs = (unsigned short)(u >> 16);
            g_Dh[idx] = *(__nv_bfloat16*)&hs;
            g_Dl[idx] = l;
        }
    } else {
        const int id = blockIdx.x - 128;
        const int b = id / 12, dchunk = id % 12;
        float s0 = g_smax[b * C + t], s1 = g_smax[b * C + 256 + t];
        float ms0 = cmask[b * C + t] ? s0 : NEGBIG;
        float ms1 = cmask[b * C + 256 + t] ? s1 : NEGBIG;
        sh_red[t] = fmaxf(ms0, ms1);
        __syncthreads();
        for (int o = 128; o; o >>= 1) {
            if (t < o) sh_red[t] = fmaxf(sh_red[t], sh_red[t + o]);
            __syncthreads();
        }
        float M = sh_red[0];
        __syncthreads();
        float e0 = expf(ms0 - M), e1 = expf(ms1 - M);
        sh_red[t] = e0 + e1;
        __syncthreads();
        for (int o = 128; o; o >>= 1) {
            if (t < o) sh_red[t] += sh_red[t + o];
            __syncthreads();
        }
        float rS = 1.f / sh_red[0];
        sh_w[t] = e0 * rS;
        sh_w[256 + t] = e1 * rS;
        __syncthreads();
        const int d0 = dchunk * 64;
        const int dl = t & 63, cs = t >> 6;
        float acc = 0.f;
        const float* base = cont + ((size_t)(b * C + cs * 128)) * D + d0 + dl;
        const float* wp = &sh_w[cs * 128];
        #pragma unroll 4
        for (int c = 0; c < 128; c++) acc += wp[c] * base[(size_t)c * D];
        float (*red2)[64] = (float (*)[64])sh_red;
        red2[cs][dl] = acc;
        __syncthreads();
        if (t < 64)
            g_cdash[b * D + d0 + t] = (red2[0][t] + red2[1][t]) + (red2[2][t] + red2[3][t]);
    }
}

// ================= K3: c2q GEMM (3-stage cp.async) + epilogue =================
#define C2Q_STAGE 27648
#define C2Q_SMEM (3 * C2Q_STAGE)   // 82944
__global__ __launch_bounds__(256, 2) void k_c2q_mma(const float* __restrict__ cont,
                                                    float* __restrict__ out) {
    extern __shared__ char dbuf[];
    __shared__ float sm_cd[128];
    float* S = (float*)dbuf;

    const int cb = blockIdx.x, dt = blockIdx.y, b = blockIdx.z;
    const int t = threadIdx.x, lane = t & 31, wid = t >> 5;
    const int wm = wid & 1, wn = wid >> 1;

    if (t < 128) sm_cd[t] = g_cdash[b * D + dt * 128 + t];

    const __nv_bfloat16* Dh = g_Dh + ((size_t)(b * C + cb * 64)) * Q;
    const __nv_bfloat16* Dl = g_Dl + ((size_t)(b * C + cb * 64)) * Q;
    const __nv_bfloat16* Qh = g_Qh + ((size_t)b * Q) * D + dt * 128;
    const __nv_bfloat16* Ql = g_Ql + ((size_t)b * Q) * D + dt * 128;

    auto AhB = [&](int s) { return (__nv_bfloat16(*)[40])(dbuf + s * C2Q_STAGE); };
    auto AlB = [&](int s) { return (__nv_bfloat16(*)[40])(dbuf + s * C2Q_STAGE + 5120); };
    auto BhB = [&](int s) { return (__nv_bfloat16(*)[136])(dbuf + s * C2Q_STAGE + 10240); };
    auto BlB = [&](int s) { return (__nv_bfloat16(*)[136])(dbuf + s * C2Q_STAGE + 18944); };

    const int ar = t >> 2, acl = t & 3;
    auto issueChunk = [&](int k0, int s) {
        cp16(&AhB(s)[ar][acl * 8], Dh + (size_t)ar * Q + k0 + acl * 8);
        cp16(&AlB(s)[ar][acl * 8], Dl + (size_t)ar * Q + k0 + acl * 8);
        __nv_bfloat16 (*Bh)[136] = BhB(s);
        __nv_bfloat16 (*Bl)[136] = BlB(s);
        #pragma unroll
        for (int i = 0; i < 2; i++) {
            int idx = t + i * 256;
            int r = idx >> 4, cl = idx & 15;
            cp16(&Bh[r][cl * 8], Qh + (size_t)(k0 + r) * D + cl * 8);
            cp16(&Bl[r][cl * 8], Ql + (size_t)(k0 + r) * D + cl * 8);
        }
    };

    float acc[2][4][4];
    #pragma unroll
    for (int i = 0; i < 2; i++)
        #pragma unroll
        for (int j = 0; j < 4; j++)
            #pragma unroll
            for (int k = 0; k < 4; k++) acc[i][j][k] = 0.f;

    issueChunk(0, 0);  CP_COMMIT();
    issueChunk(32, 1); CP_COMMIT();

    #pragma unroll
    for (int k = 0; k < 4; k++) {
        if (k < 3) { CP_WAIT(1); } else { CP_WAIT(0); }
        __syncthreads();
        const int cur = k % 3;
        __nv_bfloat16 (*Ah)[40]  = AhB(cur);
        __nv_bfloat16 (*Al)[40]  = AlB(cur);
        __nv_bfloat16 (*Bh)[136] = BhB(cur);
        __nv_bfloat16 (*Bl)[136] = BlB(cur);
        #pragma unroll
        for (int kk = 0; kk < 2; kk++) {
            const int kb = kk * 16;
            unsigned afh[2][4], afl[2][4];
            #pragma unroll
            for (int mt = 0; mt < 2; mt++) {
                ldm_x4(afh[mt], &Ah[wm * 32 + mt * 16 + (lane & 15)][kb + (lane >> 4) * 8]);
                ldm_x4(afl[mt], &Al[wm * 32 + mt * 16 + (lane & 15)][kb + (lane >> 4) * 8]);
            }
            #pragma unroll
            for (int ng = 0; ng < 2; ng++) {
                unsigned bfh[4], bfl[4];
                ldm_x4t(bfh, &Bh[kb + (lane & 15)][wn * 32 + ng * 16 + (lane >> 4) * 8]);
                ldm_x4t(bfl, &Bl[kb + (lane & 15)][wn * 32 + ng * 16 + (lane >> 4) * 8]);
                #pragma unroll
                for (int h = 0; h < 2; h++) {
                    const int nt = ng * 2 + h;
                    #pragma unroll
                    for (int mt = 0; mt < 2; mt++) {
                        mma_bf16(acc[mt][nt], afh[mt], bfh[2 * h], bfh[2 * h + 1]);
                        mma_bf16(acc[mt][nt], afh[mt], bfl[2 * h], bfl[2 * h + 1]);
                        mma_bf16(acc[mt][nt], afl[mt], bfh[2 * h], bfh[2 * h + 1]);
                    }
                }
            }
        }
        if (k + 2 < 4) { issueChunk((k + 2) * 32, (k + 2) % 3); CP_COMMIT(); }
    }
    __syncthreads();

    #pragma unroll
    for (int mt = 0; mt < 2; mt++) {
        const int r0 = wm * 32 + mt * 16 + (lane >> 2);
        #pragma unroll
        for (int nt = 0; nt < 4; nt++) {
            const int d0 = wn * 32 + nt * 8 + (lane & 3) * 2;
            *(float2*)&S[r0 * SSTRIDE + d0]       = make_float2(acc[mt][nt][0], acc[mt][nt][1]);
            *(float2*)&S[(r0 + 8) * SSTRIDE + d0] = make_float2(acc[mt][nt][2], acc[mt][nt][3]);
        }
    }
    __syncthreads();

    // epilogue with 2-deep cont prefetch
    float4 cd = *(const float4*)&sm_cd[lane * 4];
    const float* cbase = cont + ((size_t)(b * C + cb * 64 + wid * 8)) * D + dt * 128 + lane * 4;
    float4 ct_next = *(const float4*)(cbase);
    #pragma unroll
    for (int r = 0; r < 8; r++) {
        float4 ct = ct_next;
        if (r + 1 < 8) ct_next = *(const float4*)(cbase + (size_t)(r + 1) * D);
        const int row = wid * 8 + r;
        const int c = cb * 64 + row;
        float4 cq = *(const float4*)&S[row * SSTRIDE + lane * 4];
        float4 m1 = make_float4(ct.x * cq.x, ct.y * cq.y, ct.z * cq.z, ct.w * cq.w);
        float4 m2 = make_float4(ct.x * cd.x, ct.y * cd.y, ct.z * cd.z, ct.w * cd.w);
        float* ob = out + ((size_t)(b * C + c)) * OD + dt * 128 + lane * 4;
        *(float4*)(ob)         = ct;
        *(float4*)(ob + D)     = cq;
        *(float4*)(ob + 2 * D) = m1;
        *(float4*)(ob + 3 * D) = m2;
    }
}

// ---------------- launch ----------------
extern "C" void kernel_launch(void* const* d_in, const int* in_sizes, int n_in,
                              void* d_out, int out_size) {
    const float* cont  = (const float*)d_in[0];
    const int*   cmask = (const int*)d_in[1];
    const float* ques  = (const float*)d_in[2];
    const int*   qmask = (const int*)d_in[3];
    const float* SW    = (const float*)d_in[4];
    float* out = (float*)d_out;
    (void)in_sizes; (void)n_in; (void)out_size;

    cudaFuncSetAttribute(k_sim_mma, cudaFuncAttributeMaxDynamicSharedMemorySize, SIM_SMEM);
    cudaFuncSetAttribute(k_c2q_mma, cudaFuncAttributeMaxDynamicSharedMemorySize, C2Q_SMEM);

    {                           k_convQ<<<128, 256>>>(ques, SW); }
    {   dim3 g(C / 64, B);      k_sim_mma<<<g, 256, SIM_SMEM>>>(cont, SW); }
    {                           k_mid<<<512, 256>>>(cont, qmask, cmask); }
    {   dim3 g(C / 64, 6, B);   k_c2q_mma<<<g, 256, C2Q_SMEM>>>(cont, out); }
}